// round 11
// baseline (speedup 1.0000x reference)
#include <cuda_runtime.h>
#include <cuda_fp16.h>
#include <cstdint>

#define BB 8
#define SS 2048
#define DD 128
#define NTH 128                   // 4 warps per CTA
#define NCH 32                    // 64-key chunks over full key range
#define QROWS 64                  // q-rows per CTA
#define OUT_W_OFF ((size_t)BB * SS * DD)

#define RSB 272                   // smem row stride bytes (136 halfs)
#define QLO_D 17408               // Q hi->lo delta (64 rows)
#define KLO_D 17408               // K hi->lo delta

#define QH_OFF 0                  // Q hi 17408 + lo 17408
#define KH_OFF 34816              // K hi 17408 + lo 17408 (single buf)
#define VB_OFF 69632              // V hi x2 buffers (17408 each)
#define WV_OFF 104448             // winv[64] floats
#define SMEM_TOTAL 104704

__device__ __half gQh[(size_t)BB * SS * DD];
__device__ __half gQl[(size_t)BB * SS * DD];
__device__ __half gKh[(size_t)BB * SS * DD];
__device__ __half gKl[(size_t)BB * SS * DD];
__device__ __half gVh[(size_t)BB * SS * DD];

// ============================= helpers =====================================
__device__ __forceinline__ uint32_t smem_u32(const void* p) {
    uint32_t a;
    asm("{ .reg .u64 t; cvta.to.shared.u64 t, %1; cvt.u32.u64 %0, t; }" : "=r"(a) : "l"(p));
    return a;
}
__device__ __forceinline__ void cpa16(uint32_t dst, const void* src) {
    asm volatile("cp.async.cg.shared.global [%0], [%1], 16;" :: "r"(dst), "l"(src));
}
#define CPA_COMMIT() asm volatile("cp.async.commit_group;")
#define CPA_WAIT1()  asm volatile("cp.async.wait_group 1;")
#define CPA_WAIT0()  asm volatile("cp.async.wait_group 0;")

__device__ __forceinline__ void ldsm4(uint32_t& r0, uint32_t& r1, uint32_t& r2, uint32_t& r3,
                                      uint32_t a) {
    asm volatile("ldmatrix.sync.aligned.m8n8.x4.shared.b16 {%0,%1,%2,%3}, [%4];"
                 : "=r"(r0), "=r"(r1), "=r"(r2), "=r"(r3) : "r"(a));
}
__device__ __forceinline__ void ldsm4t(uint32_t& r0, uint32_t& r1, uint32_t& r2, uint32_t& r3,
                                       uint32_t a) {
    asm volatile("ldmatrix.sync.aligned.m8n8.x4.trans.shared.b16 {%0,%1,%2,%3}, [%4];"
                 : "=r"(r0), "=r"(r1), "=r"(r2), "=r"(r3) : "r"(a));
}
__device__ __forceinline__ void mma16816(float* c, uint32_t a0, uint32_t a1, uint32_t a2,
                                         uint32_t a3, uint32_t b0, uint32_t b1) {
    asm volatile("mma.sync.aligned.m16n8k16.row.col.f32.f16.f16.f32 "
                 "{%0,%1,%2,%3}, {%4,%5,%6,%7}, {%8,%9}, {%0,%1,%2,%3};"
                 : "+f"(c[0]), "+f"(c[1]), "+f"(c[2]), "+f"(c[3])
                 : "r"(a0), "r"(a1), "r"(a2), "r"(a3), "r"(b0), "r"(b1));
}
__device__ __forceinline__ void split2(float a, float b, uint32_t& hi, uint32_t& lo) {
    __half ha = __float2half_rn(a), hb = __float2half_rn(b);
    __half la = __float2half_rn(a - __half2float(ha));
    __half lb = __float2half_rn(b - __half2float(hb));
    hi = (uint32_t)__half_as_ushort(ha) | ((uint32_t)__half_as_ushort(hb) << 16);
    lo = (uint32_t)__half_as_ushort(la) | ((uint32_t)__half_as_ushort(lb) << 16);
}

// =========================== prep: fp32 -> hi/lo ===========================
__global__ void prep_split(const float* __restrict__ Q, const float* __restrict__ K,
                           const float* __restrict__ V) {
    size_t i = (size_t)blockIdx.x * 256 + threadIdx.x;
    if (blockIdx.y == 0) {
        float x = Q[i];
        __half h = __float2half_rn(x);
        gQh[i] = h;
        gQl[i] = __float2half_rn(x - __half2float(h));
    } else if (blockIdx.y == 1) {
        float x = K[i];
        __half h = __float2half_rn(x);
        gKh[i] = h;
        gKl[i] = __float2half_rn(x - __half2float(h));
    } else {
        gVh[i] = __float2half_rn(V[i]);       // V lo unused (2-term PV)
    }
}

// stage 64-row hi+lo chunk (128 threads)
__device__ __forceinline__ void stage64g(int t, uint32_t dH,
                                         const __half* sH, const __half* sL) {
    #pragma unroll
    for (int i = 0; i < 8; i++) {
        int idx = t + NTH * i;                // 0..1023
        int r = idx >> 4, c = idx & 15;
        uint32_t off = (uint32_t)(r * RSB + c * 16);
        cpa16(dH + off, sH + (size_t)r * DD + c * 8);
        cpa16(dH + KLO_D + off, sL + (size_t)r * DD + c * 8);
    }
}
// stage 64-row hi-only chunk
__device__ __forceinline__ void stage64h(int t, uint32_t dH, const __half* sH) {
    #pragma unroll
    for (int i = 0; i < 8; i++) {
        int idx = t + NTH * i;
        int r = idx >> 4, c = idx & 15;
        cpa16(dH + (uint32_t)(r * RSB + c * 16), sH + (size_t)r * DD + c * 8);
    }
}

// ============================= main kernel =================================
__global__ __launch_bounds__(NTH, 2)
void attn_mma(float* __restrict__ out) {
    extern __shared__ __align__(1024) unsigned char sm[];
    const uint32_t sb = smem_u32(sm);
    const int t = threadIdx.x, lane = t & 31, w = t >> 5;
    const int b = blockIdx.x >> 5, q0 = (blockIdx.x & 31) * QROWS;

    const size_t rowbase = (size_t)b * SS;
    const __half* qh = gQh + (rowbase + q0) * DD;
    const __half* ql = gQl + (rowbase + q0) * DD;
    const __half* kh = gKh + rowbase * DD;
    const __half* kl = gKl + rowbase * DD;
    const __half* vh = gVh + rowbase * DD;

    const uint32_t kbH = sb + KH_OFF;
    const uint32_t vb0 = sb + VB_OFF;

    const uint32_t qa0 = sb + QH_OFF +
        (uint32_t)((w * 16 + (lane & 7) + ((lane >> 3) & 1) * 8) * RSB + ((lane >> 4) & 1) * 16);
    const uint32_t krowoff =
        (uint32_t)(((lane & 7) + ((lane >> 4) & 1) * 8) * RSB + ((lane >> 3) & 1) * 16);
    const uint32_t vrowoff =
        (uint32_t)(((lane & 7) + ((lane >> 3) & 1) * 8) * RSB + ((lane >> 4) & 1) * 16);
    const int r0q = w * 16 + (lane >> 2);     // thread rows: r0q, r0q+8

    // ---- prologue: Q hi+lo + pre-pass K0 hi (into V buffers) ----
    #pragma unroll
    for (int i = 0; i < 8; i++) {
        int idx = t + NTH * i;                // 0..1023
        int r = idx >> 4, c = idx & 15;
        uint32_t off = (uint32_t)(r * RSB + c * 16);
        cpa16(sb + QH_OFF + off, qh + (size_t)r * DD + c * 8);
        cpa16(sb + QH_OFF + QLO_D + off, ql + (size_t)r * DD + c * 8);
    }
    stage64h(t, vb0, kh);
    CPA_COMMIT();
    CPA_WAIT0();
    __syncthreads();

    // ================= pre-pass: M~ = rowmax(Qhi Khi^T) ====================
    float mm0 = -3.402823466e38f, mm1 = -3.402823466e38f;
    #pragma unroll 1
    for (int i = 0; i < NCH; i++) {
        if (i + 1 < NCH)
            stage64h(t, vb0 + (uint32_t)((i + 1) & 1) * KLO_D,
                     kh + (size_t)(i + 1) * 64 * DD);
        CPA_COMMIT();
        CPA_WAIT1();
        __syncthreads();
        const uint32_t kb = vb0 + (uint32_t)(i & 1) * KLO_D;
        float S[8][4];
        #pragma unroll
        for (int r = 0; r < 8; r++) { S[r][0] = 0.f; S[r][1] = 0.f; S[r][2] = 0.f; S[r][3] = 0.f; }
        #pragma unroll
        for (int kt = 0; kt < 8; kt++) {
            uint32_t q0_, q1_, q2_, q3_;
            ldsm4(q0_, q1_, q2_, q3_, qa0 + kt * 32);
            #pragma unroll
            for (int ng = 0; ng < 4; ng++) {
                uint32_t ka = kb + (uint32_t)(ng * 16 * RSB) + krowoff + kt * 32;
                uint32_t k0, k1, k2, k3;
                ldsm4(k0, k1, k2, k3, ka);
                mma16816(S[2 * ng], q0_, q1_, q2_, q3_, k0, k1);
                mma16816(S[2 * ng + 1], q0_, q1_, q2_, q3_, k2, k3);
            }
        }
        #pragma unroll
        for (int nt = 0; nt < 8; nt++) {
            mm0 = fmaxf(mm0, fmaxf(S[nt][0], S[nt][1]));
            mm1 = fmaxf(mm1, fmaxf(S[nt][2], S[nt][3]));
        }
        __syncthreads();
    }
    mm0 = fmaxf(mm0, __shfl_xor_sync(0xffffffffu, mm0, 1));
    mm0 = fmaxf(mm0, __shfl_xor_sync(0xffffffffu, mm0, 2));
    mm1 = fmaxf(mm1, __shfl_xor_sync(0xffffffffu, mm1, 1));
    mm1 = fmaxf(mm1, __shfl_xor_sync(0xffffffffu, mm1, 2));
    const float Ms0 = mm0 + 0.25f;            // safe fixed shift
    const float Ms1 = mm1 + 0.25f;

    // ---- main prologue: K0 hi+lo + V0, then V1 ----
    stage64g(t, kbH, kh, kl);
    stage64h(t, vb0, vh);
    CPA_COMMIT();
    stage64h(t, vb0 + KLO_D, vh + (size_t)64 * DD);
    CPA_COMMIT();

    float O[16][4];
    #pragma unroll
    for (int n = 0; n < 16; n++) { O[n][0] = 0.f; O[n][1] = 0.f; O[n][2] = 0.f; O[n][3] = 0.f; }
    float l0 = 0.f, l1 = 0.f;

    float* wrow0 = out + OUT_W_OFF + (rowbase + q0 + r0q) * SS + 2 * (lane & 3);
    float* wrow1 = wrow0 + (size_t)8 * SS;

    // =================== main loop: fixed-shift softmax ====================
    #pragma unroll 1
    for (int j = 0; j < NCH; j++) {
        CPA_WAIT1();                           // K(j), V(j) landed
        __syncthreads();

        // S(j): 16 rows x 64 keys, 3-term
        float S[8][4];
        #pragma unroll
        for (int r = 0; r < 8; r++) { S[r][0] = 0.f; S[r][1] = 0.f; S[r][2] = 0.f; S[r][3] = 0.f; }
        #pragma unroll
        for (int kt = 0; kt < 8; kt++) {
            uint32_t qh0, qh1, qh2, qh3, ql0, ql1, ql2, ql3;
            ldsm4(qh0, qh1, qh2, qh3, qa0 + kt * 32);
            ldsm4(ql0, ql1, ql2, ql3, qa0 + kt * 32 + QLO_D);
            #pragma unroll
            for (int ng = 0; ng < 4; ng++) {
                uint32_t ka = kbH + (uint32_t)(ng * 16 * RSB) + krowoff + kt * 32;
                uint32_t k0, k1, k2, k3, m0_, m1_, m2_, m3_;
                ldsm4(k0, k1, k2, k3, ka);
                ldsm4(m0_, m1_, m2_, m3_, ka + KLO_D);
                mma16816(S[2 * ng], qh0, qh1, qh2, qh3, k0, k1);
                mma16816(S[2 * ng], ql0, ql1, ql2, ql3, k0, k1);
                mma16816(S[2 * ng], qh0, qh1, qh2, qh3, m0_, m1_);
                mma16816(S[2 * ng + 1], qh0, qh1, qh2, qh3, k2, k3);
                mma16816(S[2 * ng + 1], ql0, ql1, ql2, ql3, k2, k3);
                mma16816(S[2 * ng + 1], qh0, qh1, qh2, qh3, m2_, m3_);
            }
        }
        __syncthreads();                       // K(j) consumed
        if (j + 1 < NCH)
            stage64g(t, kbH, kh + (size_t)(j + 1) * 64 * DD,
                     kl + (size_t)(j + 1) * 64 * DD);
        CPA_COMMIT();

        // U = e^{s - M*}; accumulate l; write raw U
        #pragma unroll
        for (int nt = 0; nt < 8; nt++) {
            S[nt][0] = __expf(S[nt][0] - Ms0);
            S[nt][1] = __expf(S[nt][1] - Ms0);
            S[nt][2] = __expf(S[nt][2] - Ms1);
            S[nt][3] = __expf(S[nt][3] - Ms1);
            l0 += S[nt][0] + S[nt][1];
            l1 += S[nt][2] + S[nt][3];
        }
        #pragma unroll
        for (int nt = 0; nt < 8; nt++) {
            *(float2*)(wrow0 + j * 64 + nt * 8) = make_float2(S[nt][0], S[nt][1]);
            *(float2*)(wrow1 + j * 64 + nt * 8) = make_float2(S[nt][2], S[nt][3]);
        }

        // O += P V (2-term: PhVh + PlVh)
        const uint32_t vbH = vb0 + (uint32_t)(j & 1) * KLO_D;
        #pragma unroll
        for (int kt = 0; kt < 4; kt++) {
            uint32_t ph0, ph1, ph2, ph3, pl0, pl1, pl2, pl3;
            split2(S[2 * kt][0], S[2 * kt][1], ph0, pl0);
            split2(S[2 * kt][2], S[2 * kt][3], ph1, pl1);
            split2(S[2 * kt + 1][0], S[2 * kt + 1][1], ph2, pl2);
            split2(S[2 * kt + 1][2], S[2 * kt + 1][3], ph3, pl3);
            #pragma unroll
            for (int ng = 0; ng < 8; ng++) {
                uint32_t va = vbH + (uint32_t)(kt * 16 * RSB) + vrowoff + ng * 32;
                uint32_t x0, x1, x2, x3;
                ldsm4t(x0, x1, x2, x3, va);
                mma16816(O[2 * ng], ph0, ph1, ph2, ph3, x0, x1);
                mma16816(O[2 * ng], pl0, pl1, pl2, pl3, x0, x1);
                mma16816(O[2 * ng + 1], ph0, ph1, ph2, ph3, x2, x3);
                mma16816(O[2 * ng + 1], pl0, pl1, pl2, pl3, x2, x3);
            }
        }
        __syncthreads();                       // V(j) consumed
        if (j + 2 < NCH)
            stage64h(t, vb0 + (uint32_t)(j & 1) * KLO_D,
                     vh + (size_t)(j + 2) * 64 * DD);
        CPA_COMMIT();
    }

    // =========================== epilogue ==================================
    l0 += __shfl_xor_sync(0xffffffffu, l0, 1);
    l0 += __shfl_xor_sync(0xffffffffu, l0, 2);
    l1 += __shfl_xor_sync(0xffffffffu, l1, 1);
    l1 += __shfl_xor_sync(0xffffffffu, l1, 2);
    const float linv0 = 1.0f / l0, linv1 = 1.0f / l1;

    float* wvs = (float*)(sm + WV_OFF);
    if ((lane & 3) == 0) {
        wvs[r0q] = linv0;
        wvs[r0q + 8] = linv1;
    }

    float* orow0 = out + (rowbase + q0 + r0q) * DD + 2 * (lane & 3);
    float* orow1 = orow0 + (size_t)8 * DD;
    #pragma unroll
    for (int nt = 0; nt < 16; nt++) {
        *(float2*)(orow0 + nt * 8) = make_float2(O[nt][0] * linv0, O[nt][1] * linv0);
        *(float2*)(orow1 + nt * 8) = make_float2(O[nt][2] * linv1, O[nt][3] * linv1);
    }
    __syncthreads();

    // ============= W fixup: pure multiply (no exp) =========================
    float4* wbase = (float4*)(out + OUT_W_OFF + (rowbase + q0) * SS);
    #pragma unroll 4
    for (int i = 0; i < 256; i++) {
        int fi = t + NTH * i;                  // 0..32767
        float wv = wvs[fi >> 9];               // 512 float4 per row
        float4 v = wbase[fi];
        v.x *= wv; v.y *= wv; v.z *= wv; v.w *= wv;
        wbase[fi] = v;
    }
}

// ===========================================================================
extern "C" void kernel_launch(void* const* d_in, const int* in_sizes, int n_in,
                              void* d_out, int out_size) {
    const float* Q = (const float*)d_in[0];
    const float* K = (const float*)d_in[1];
    const float* V = (const float*)d_in[2];
    float* out = (float*)d_out;

    cudaFuncSetAttribute(attn_mma, cudaFuncAttributeMaxDynamicSharedMemorySize, SMEM_TOTAL);

    prep_split<<<dim3((BB * SS * DD) / 256, 3), 256>>>(Q, K, V);
    attn_mma<<<BB * (SS / QROWS), NTH, SMEM_TOTAL>>>(out);
}